// round 2
// baseline (speedup 1.0000x reference)
#include <cuda_runtime.h>
#include <math.h>
#include <stdint.h>

// Problem constants (fixed shapes)
#define NROW   24576          // B*T
#define KDIM   512            // DIM
#define GV     640            // G*V
#define VNUM   320            // V per group
#define VD     128            // var_dim per group
#define NGROUP 2
#define OUT_MAIN (NROW * (NGROUP * VD))   // 24576*256
#define TAU    2.0f
#define EPSQ   1e-7f

// Scratch (static device globals; no runtime allocation)
__device__ float g_logits[(size_t)NROW * GV];
__device__ float g_prob[GV];
__device__ float g_cnt[GV];

// ---------------------------------------------------------------------------
// Kernel 0: zero accumulators
// ---------------------------------------------------------------------------
__global__ void init_kernel() {
    int t = threadIdx.x;
    if (t < GV) { g_prob[t] = 0.0f; g_cnt[t] = 0.0f; }
}

// ---------------------------------------------------------------------------
// Kernel 1: SGEMM  logits = x @ W^T + b   (fp32, classic 128x128x8, dbl-buffer)
// ---------------------------------------------------------------------------
#define BM 128
#define BN 128
#define BK 8

__global__ __launch_bounds__(256, 2)
void sgemm_kernel(const float* __restrict__ A,      // [NROW, KDIM]
                  const float* __restrict__ W,      // [GV, KDIM]
                  const float* __restrict__ bias)   // [GV]
{
    __shared__ float As[2][BK][BM];
    __shared__ float Bs[2][BK][BN];

    const int tid = threadIdx.x;
    const int bn  = blockIdx.x;   // 0..4
    const int bm  = blockIdx.y;   // 0..191
    const int tx  = tid & 15;
    const int ty  = tid >> 4;

    // global-load assignment: each thread loads one float4 per tile per matrix
    const int lm = tid >> 1;          // 0..127  (row within tile)
    const int lk = (tid & 1) * 4;     // 0 or 4  (k offset within BK)

    const float* Ag = A + (size_t)(bm * BM + lm) * KDIM + lk;
    const float* Wg = W + (size_t)(bn * BN + lm) * KDIM + lk;

    float4 aR = *(const float4*)Ag;
    float4 bR = *(const float4*)Wg;
    As[0][lk + 0][lm] = aR.x; As[0][lk + 1][lm] = aR.y;
    As[0][lk + 2][lm] = aR.z; As[0][lk + 3][lm] = aR.w;
    Bs[0][lk + 0][lm] = bR.x; Bs[0][lk + 1][lm] = bR.y;
    Bs[0][lk + 2][lm] = bR.z; Bs[0][lk + 3][lm] = bR.w;

    float acc[8][8];
#pragma unroll
    for (int i = 0; i < 8; i++)
#pragma unroll
        for (int j = 0; j < 8; j++) acc[i][j] = 0.0f;

    const int NK = KDIM / BK;   // 64
    for (int kt = 0; kt < NK; kt++) {
        __syncthreads();
        const int cur = kt & 1;
        if (kt + 1 < NK) {
            aR = *(const float4*)(Ag + (kt + 1) * BK);
            bR = *(const float4*)(Wg + (kt + 1) * BK);
        }
#pragma unroll
        for (int kk = 0; kk < BK; kk++) {
            float a[8], b[8];
            *(float4*)(a)     = *(const float4*)&As[cur][kk][ty * 8];
            *(float4*)(a + 4) = *(const float4*)&As[cur][kk][ty * 8 + 4];
            *(float4*)(b)     = *(const float4*)&Bs[cur][kk][tx * 8];
            *(float4*)(b + 4) = *(const float4*)&Bs[cur][kk][tx * 8 + 4];
#pragma unroll
            for (int i = 0; i < 8; i++)
#pragma unroll
                for (int j = 0; j < 8; j++)
                    acc[i][j] = fmaf(a[i], b[j], acc[i][j]);
        }
        if (kt + 1 < NK) {
            const int nxt = cur ^ 1;
            As[nxt][lk + 0][lm] = aR.x; As[nxt][lk + 1][lm] = aR.y;
            As[nxt][lk + 2][lm] = aR.z; As[nxt][lk + 3][lm] = aR.w;
            Bs[nxt][lk + 0][lm] = bR.x; Bs[nxt][lk + 1][lm] = bR.y;
            Bs[nxt][lk + 2][lm] = bR.z; Bs[nxt][lk + 3][lm] = bR.w;
        }
    }

    const int row0 = bm * BM + ty * 8;
    const int col0 = bn * BN + tx * 8;
    float bb[8];
#pragma unroll
    for (int j = 0; j < 8; j++) bb[j] = __ldg(&bias[col0 + j]);
#pragma unroll
    for (int i = 0; i < 8; i++) {
        float4 v0 = make_float4(acc[i][0] + bb[0], acc[i][1] + bb[1],
                                acc[i][2] + bb[2], acc[i][3] + bb[3]);
        float4 v1 = make_float4(acc[i][4] + bb[4], acc[i][5] + bb[5],
                                acc[i][6] + bb[6], acc[i][7] + bb[7]);
        float* Crow = g_logits + (size_t)(row0 + i) * GV + col0;
        *(float4*)(Crow)     = v0;
        *(float4*)(Crow + 4) = v1;
    }
}

// ---------------------------------------------------------------------------
// Kernel 2: fused epilogue — argmax (hard), argmax(logits+gumbel) -> gather,
// stable softmax accumulation (shared -> global atomics), output write.
// 32 rows per block, 8 warps (4 rows each), 256 threads.
// ---------------------------------------------------------------------------
__global__ __launch_bounds__(256)
void epilogue_kernel(const float* __restrict__ gumbel,   // [NROW, GV]
                     const float* __restrict__ codebook, // [GV, VD]
                     float* __restrict__ out)            // [NROW, 256]
{
    __shared__ float sProb[GV];
    __shared__ float sCnt[GV];
    __shared__ int   sIdx[32][2];

    const int tid  = threadIdx.x;
    const int warp = tid >> 5;
    const int lane = tid & 31;
    const int n0   = blockIdx.x * 32;

    for (int i = tid; i < GV; i += 256) { sProb[i] = 0.0f; sCnt[i] = 0.0f; }
    __syncthreads();

    for (int rr = 0; rr < 4; rr++) {
        const int n = n0 + warp * 4 + rr;
#pragma unroll
        for (int g = 0; g < NGROUP; g++) {
            const float* Lg = g_logits + (size_t)n * GV + g * VNUM;
            const float* Gg = gumbel   + (size_t)n * GV + g * VNUM;
            float lv[10];
            float mx  = -INFINITY; int mi  = 0;   // raw-logit argmax
            float gmx = -INFINITY; int gmi = 0;   // gumbel argmax
#pragma unroll
            for (int j = 0; j < 10; j++) {
                const int v = lane + 32 * j;
                const float l = Lg[v];
                lv[j] = l;
                if (l > mx)  { mx = l;  mi = v; }     // ascending v => first index
                const float ge = l + Gg[v];
                if (ge > gmx) { gmx = ge; gmi = v; }
            }
            // warp argmax reductions (larger value wins; ties -> smaller index)
#pragma unroll
            for (int off = 16; off; off >>= 1) {
                float ox  = __shfl_xor_sync(0xffffffffu, mx, off);
                int   oi  = __shfl_xor_sync(0xffffffffu, mi, off);
                if (ox > mx || (ox == mx && oi < mi)) { mx = ox; mi = oi; }
                float ogx = __shfl_xor_sync(0xffffffffu, gmx, off);
                int   ogi = __shfl_xor_sync(0xffffffffu, gmi, off);
                if (ogx > gmx || (ogx == gmx && ogi < gmi)) { gmx = ogx; gmi = ogi; }
            }
            // stable softmax sum
            float ev[10];
            float s = 0.0f;
#pragma unroll
            for (int j = 0; j < 10; j++) { ev[j] = __expf(lv[j] - mx); s += ev[j]; }
#pragma unroll
            for (int off = 16; off; off >>= 1)
                s += __shfl_xor_sync(0xffffffffu, s, off);
            const float inv = 1.0f / s;
#pragma unroll
            for (int j = 0; j < 10; j++)
                atomicAdd(&sProb[g * VNUM + lane + 32 * j], ev[j] * inv);
            if (lane == 0) {
                atomicAdd(&sCnt[g * VNUM + mi], 1.0f);
                sIdx[warp * 4 + rr][g] = gmi;
            }
        }
    }
    __syncthreads();

    for (int i = tid; i < GV; i += 256) {
        atomicAdd(&g_prob[i], sProb[i]);
        atomicAdd(&g_cnt[i],  sCnt[i]);
    }

    // Output gather: 32 rows * 256 floats = 2048 float4
#pragma unroll
    for (int i = 0; i < 8; i++) {
        const int q   = tid + i * 256;
        const int row = q >> 6;          // 64 float4 per row
        const int f4  = q & 63;
        const int g   = f4 >> 5;
        const int idx = sIdx[row][g];
        const float4* src = (const float4*)(codebook + (size_t)(g * VNUM + idx) * VD)
                            + (f4 & 31);
        ((float4*)(out + (size_t)(n0 + row) * 256))[f4] = __ldg(src);
    }
}

// ---------------------------------------------------------------------------
// Kernel 3: finalize perplexity scalars
// ---------------------------------------------------------------------------
__global__ void finalize_kernel(float* __restrict__ out, int out_size) {
    const int tid  = threadIdx.x;   // 640 threads
    const int warp = tid >> 5;      // 0..19 (groups split exactly at warp 10)
    const int lane = tid & 31;
    __shared__ float wp[20], wh[20];

    float pterm = 0.0f, hterm = 0.0f;
    if (tid < GV) {
        const float p = g_prob[tid] * (1.0f / (float)NROW);
        const float h = g_cnt[tid]  * (1.0f / (float)NROW);
        pterm = p * logf(p + EPSQ);
        hterm = h * logf(h + EPSQ);
    }
#pragma unroll
    for (int off = 16; off; off >>= 1) {
        pterm += __shfl_xor_sync(0xffffffffu, pterm, off);
        hterm += __shfl_xor_sync(0xffffffffu, hterm, off);
    }
    if (lane == 0) { wp[warp] = pterm; wh[warp] = hterm; }
    __syncthreads();
    if (tid == 0) {
        float p0 = 0.f, p1 = 0.f, h0 = 0.f, h1 = 0.f;
        for (int w = 0; w < 10; w++)  { p0 += wp[w]; h0 += wh[w]; }
        for (int w = 10; w < 20; w++) { p1 += wp[w]; h1 += wh[w]; }
        const float code_pplx = expf(-h0) + expf(-h1);
        const float prob_pplx = expf(-p0) + expf(-p1);
        if (out_size > OUT_MAIN)     out[OUT_MAIN]     = code_pplx;
        if (out_size > OUT_MAIN + 1) out[OUT_MAIN + 1] = prob_pplx;
    }
}

// ---------------------------------------------------------------------------
extern "C" void kernel_launch(void* const* d_in, const int* in_sizes, int n_in,
                              void* d_out, int out_size)
{
    const float* x    = (const float*)d_in[0];   // [16,1536,512]
    const float* W    = (const float*)d_in[1];   // [640,512]
    const float* bias = (const float*)d_in[2];   // [640]
    const float* cb   = (const float*)d_in[3];   // [1,640,128]
    const float* gum  = (const float*)d_in[4];   // [24576,2,320]
    float* out = (float*)d_out;

    init_kernel<<<1, GV>>>();

    dim3 grid(GV / BN, NROW / BM);               // (5, 192)
    sgemm_kernel<<<grid, 256>>>(x, W, bias);

    epilogue_kernel<<<NROW / 32, 256>>>(gum, cb, out);

    finalize_kernel<<<1, GV>>>(out, out_size);
}

// round 4
// speedup vs baseline: 1.0045x; 1.0045x over previous
#include <cuda_runtime.h>
#include <math.h>
#include <stdint.h>

// Problem constants (fixed shapes)
#define NROW   24576          // B*T
#define KDIM   512            // DIM
#define GV     640            // G*V
#define VNUM   320            // V per group
#define VD     128            // var_dim per group
#define NGROUP 2
#define OUT_MAIN (NROW * (NGROUP * VD))   // 24576*256
#define TAU    2.0f
#define EPSQ   1e-7f

// Scratch (static device globals; no runtime allocation)
__device__ float g_logits[(size_t)NROW * GV];
__device__ float g_prob[GV];
__device__ float g_cnt[GV];

// ---------------------------------------------------------------------------
// Kernel 0: zero accumulators
// ---------------------------------------------------------------------------
__global__ void init_kernel() {
    int t = threadIdx.x;
    if (t < GV) { g_prob[t] = 0.0f; g_cnt[t] = 0.0f; }
}

// ---------------------------------------------------------------------------
// Kernel 1: SGEMM  logits = x @ W^T + b
// fp32 via packed fma.rn.f32x2 (FFMA2), operands carried as b64 ("l" regs).
// 128x128x8 tiles, double-buffered smem, 256 threads, 8x8 per thread.
// ---------------------------------------------------------------------------
#define BM 128
#define BN 128
#define BK 8

__global__ __launch_bounds__(256, 2)
void sgemm_kernel(const float* __restrict__ A,      // [NROW, KDIM]
                  const float* __restrict__ W,      // [GV, KDIM]
                  const float* __restrict__ bias)   // [GV]
{
    __shared__ float As[2][BK][BM];
    __shared__ float Bs[2][BK][BN];

    const int tid = threadIdx.x;
    const int bn  = blockIdx.x;   // 0..4
    const int bm  = blockIdx.y;   // 0..191
    const int tx  = tid & 15;
    const int ty  = tid >> 4;

    // global-load assignment: each thread loads one float4 per tile per matrix
    const int lm = tid >> 1;          // 0..127  (row within tile)
    const int lk = (tid & 1) * 4;     // 0 or 4  (k offset within BK)

    const float* Ag = A + (size_t)(bm * BM + lm) * KDIM + lk;
    const float* Wg = W + (size_t)(bn * BN + lm) * KDIM + lk;

    float4 aR = *(const float4*)Ag;
    float4 bR = *(const float4*)Wg;
    As[0][lk + 0][lm] = aR.x; As[0][lk + 1][lm] = aR.y;
    As[0][lk + 2][lm] = aR.z; As[0][lk + 3][lm] = aR.w;
    Bs[0][lk + 0][lm] = bR.x; Bs[0][lk + 1][lm] = bR.y;
    Bs[0][lk + 2][lm] = bR.z; Bs[0][lk + 3][lm] = bR.w;

    // Packed accumulators: acc2[ip][j] holds rows (ty*8+2ip, ty*8+2ip+1), col tx*8+j
    unsigned long long acc2[4][8];
#pragma unroll
    for (int ip = 0; ip < 4; ip++)
#pragma unroll
        for (int j = 0; j < 8; j++) acc2[ip][j] = 0ull;   // (0.f, 0.f)

    const int NK = KDIM / BK;   // 64
    for (int kt = 0; kt < NK; kt++) {
        __syncthreads();
        const int cur = kt & 1;
        if (kt + 1 < NK) {
            aR = *(const float4*)(Ag + (kt + 1) * BK);
            bR = *(const float4*)(Wg + (kt + 1) * BK);
        }
#pragma unroll
        for (int kk = 0; kk < BK; kk++) {
            // A pairs come packed for free: 64-bit loads of consecutive floats
            const unsigned long long* ap =
                (const unsigned long long*)&As[cur][kk][ty * 8];
            unsigned long long a2[4];
            a2[0] = ap[0]; a2[1] = ap[1]; a2[2] = ap[2]; a2[3] = ap[3];

            float b[8];
            *(float4*)(b)     = *(const float4*)&Bs[cur][kk][tx * 8];
            *(float4*)(b + 4) = *(const float4*)&Bs[cur][kk][tx * 8 + 4];
            unsigned long long bd[8];
#pragma unroll
            for (int j = 0; j < 8; j++)
                asm("mov.b64 %0, {%1, %1};" : "=l"(bd[j]) : "f"(b[j]));

#pragma unroll
            for (int ip = 0; ip < 4; ip++)
#pragma unroll
                for (int j = 0; j < 8; j++)
                    asm("fma.rn.f32x2 %0, %1, %2, %0;"
                        : "+l"(acc2[ip][j]) : "l"(a2[ip]), "l"(bd[j]));
        }
        if (kt + 1 < NK) {
            const int nxt = cur ^ 1;
            As[nxt][lk + 0][lm] = aR.x; As[nxt][lk + 1][lm] = aR.y;
            As[nxt][lk + 2][lm] = aR.z; As[nxt][lk + 3][lm] = aR.w;
            Bs[nxt][lk + 0][lm] = bR.x; Bs[nxt][lk + 1][lm] = bR.y;
            Bs[nxt][lk + 2][lm] = bR.z; Bs[nxt][lk + 3][lm] = bR.w;
        }
    }

    const int row0 = bm * BM + ty * 8;
    const int col0 = bn * BN + tx * 8;
    float bb[8];
#pragma unroll
    for (int j = 0; j < 8; j++) bb[j] = __ldg(&bias[col0 + j]);

#pragma unroll
    for (int ip = 0; ip < 4; ip++) {
        float lo[8], hi[8];
#pragma unroll
        for (int j = 0; j < 8; j++)
            asm("mov.b64 {%0, %1}, %2;" : "=f"(lo[j]), "=f"(hi[j]) : "l"(acc2[ip][j]));
        float* C0 = g_logits + (size_t)(row0 + 2 * ip)     * GV + col0;
        float* C1 = g_logits + (size_t)(row0 + 2 * ip + 1) * GV + col0;
        *(float4*)(C0)     = make_float4(lo[0] + bb[0], lo[1] + bb[1], lo[2] + bb[2], lo[3] + bb[3]);
        *(float4*)(C0 + 4) = make_float4(lo[4] + bb[4], lo[5] + bb[5], lo[6] + bb[6], lo[7] + bb[7]);
        *(float4*)(C1)     = make_float4(hi[0] + bb[0], hi[1] + bb[1], hi[2] + bb[2], hi[3] + bb[3]);
        *(float4*)(C1 + 4) = make_float4(hi[4] + bb[4], hi[5] + bb[5], hi[6] + bb[6], hi[7] + bb[7]);
    }
}

// ---------------------------------------------------------------------------
// Kernel 2: fused epilogue — argmax (hard), argmax(logits+gumbel) -> gather,
// stable softmax accumulation (shared -> global atomics), output write.
// 32 rows per block, 8 warps (4 rows each), 256 threads.
// ---------------------------------------------------------------------------
__global__ __launch_bounds__(256)
void epilogue_kernel(const float* __restrict__ gumbel,   // [NROW, GV]
                     const float* __restrict__ codebook, // [GV, VD]
                     float* __restrict__ out)            // [NROW, 256]
{
    __shared__ float sProb[GV];
    __shared__ float sCnt[GV];
    __shared__ int   sIdx[32][2];

    const int tid  = threadIdx.x;
    const int warp = tid >> 5;
    const int lane = tid & 31;
    const int n0   = blockIdx.x * 32;

    for (int i = tid; i < GV; i += 256) { sProb[i] = 0.0f; sCnt[i] = 0.0f; }
    __syncthreads();

    for (int rr = 0; rr < 4; rr++) {
        const int n = n0 + warp * 4 + rr;
#pragma unroll
        for (int g = 0; g < NGROUP; g++) {
            const float* Lg = g_logits + (size_t)n * GV + g * VNUM;
            const float* Gg = gumbel   + (size_t)n * GV + g * VNUM;
            float lv[10];
            float mx  = -INFINITY; int mi  = 0;   // raw-logit argmax
            float gmx = -INFINITY; int gmi = 0;   // gumbel argmax
#pragma unroll
            for (int j = 0; j < 10; j++) {
                const int v = lane + 32 * j;
                const float l = Lg[v];
                lv[j] = l;
                if (l > mx)  { mx = l;  mi = v; }     // ascending v => first index
                const float ge = l + Gg[v];
                if (ge > gmx) { gmx = ge; gmi = v; }
            }
            // warp argmax reductions (larger value wins; ties -> smaller index)
#pragma unroll
            for (int off = 16; off; off >>= 1) {
                float ox  = __shfl_xor_sync(0xffffffffu, mx, off);
                int   oi  = __shfl_xor_sync(0xffffffffu, mi, off);
                if (ox > mx || (ox == mx && oi < mi)) { mx = ox; mi = oi; }
                float ogx = __shfl_xor_sync(0xffffffffu, gmx, off);
                int   ogi = __shfl_xor_sync(0xffffffffu, gmi, off);
                if (ogx > gmx || (ogx == gmx && ogi < gmi)) { gmx = ogx; gmi = ogi; }
            }
            // stable softmax sum
            float ev[10];
            float s = 0.0f;
#pragma unroll
            for (int j = 0; j < 10; j++) { ev[j] = __expf(lv[j] - mx); s += ev[j]; }
#pragma unroll
            for (int off = 16; off; off >>= 1)
                s += __shfl_xor_sync(0xffffffffu, s, off);
            const float inv = 1.0f / s;
#pragma unroll
            for (int j = 0; j < 10; j++)
                atomicAdd(&sProb[g * VNUM + lane + 32 * j], ev[j] * inv);
            if (lane == 0) {
                atomicAdd(&sCnt[g * VNUM + mi], 1.0f);
                sIdx[warp * 4 + rr][g] = gmi;
            }
        }
    }
    __syncthreads();

    for (int i = tid; i < GV; i += 256) {
        atomicAdd(&g_prob[i], sProb[i]);
        atomicAdd(&g_cnt[i],  sCnt[i]);
    }

    // Output gather: 32 rows * 256 floats = 2048 float4
#pragma unroll
    for (int i = 0; i < 8; i++) {
        const int q   = tid + i * 256;
        const int row = q >> 6;          // 64 float4 per row
        const int f4  = q & 63;
        const int g   = f4 >> 5;
        const int idx = sIdx[row][g];
        const float4* src = (const float4*)(codebook + (size_t)(g * VNUM + idx) * VD)
                            + (f4 & 31);
        ((float4*)(out + (size_t)(n0 + row) * 256))[f4] = __ldg(src);
    }
}

// ---------------------------------------------------------------------------
// Kernel 3: finalize perplexity scalars
// ---------------------------------------------------------------------------
__global__ void finalize_kernel(float* __restrict__ out, int out_size) {
    const int tid  = threadIdx.x;   // 640 threads
    const int warp = tid >> 5;      // 0..19 (groups split exactly at warp 10)
    const int lane = tid & 31;
    __shared__ float wp[20], wh[20];

    float pterm = 0.0f, hterm = 0.0f;
    if (tid < GV) {
        const float p = g_prob[tid] * (1.0f / (float)NROW);
        const float h = g_cnt[tid]  * (1.0f / (float)NROW);
        pterm = p * logf(p + EPSQ);
        hterm = h * logf(h + EPSQ);
    }
#pragma unroll
    for (int off = 16; off; off >>= 1) {
        pterm += __shfl_xor_sync(0xffffffffu, pterm, off);
        hterm += __shfl_xor_sync(0xffffffffu, hterm, off);
    }
    if (lane == 0) { wp[warp] = pterm; wh[warp] = hterm; }
    __syncthreads();
    if (tid == 0) {
        float p0 = 0.f, p1 = 0.f, h0 = 0.f, h1 = 0.f;
        for (int w = 0; w < 10; w++)  { p0 += wp[w]; h0 += wh[w]; }
        for (int w = 10; w < 20; w++) { p1 += wp[w]; h1 += wh[w]; }
        const float code_pplx = expf(-h0) + expf(-h1);
        const float prob_pplx = expf(-p0) + expf(-p1);
        if (out_size > OUT_MAIN)     out[OUT_MAIN]     = code_pplx;
        if (out_size > OUT_MAIN + 1) out[OUT_MAIN + 1] = prob_pplx;
    }
}

// ---------------------------------------------------------------------------
extern "C" void kernel_launch(void* const* d_in, const int* in_sizes, int n_in,
                              void* d_out, int out_size)
{
    const float* x    = (const float*)d_in[0];   // [16,1536,512]
    const float* W    = (const float*)d_in[1];   // [640,512]
    const float* bias = (const float*)d_in[2];   // [640]
    const float* cb   = (const float*)d_in[3];   // [1,640,128]
    const float* gum  = (const float*)d_in[4];   // [24576,2,320]
    float* out = (float*)d_out;

    init_kernel<<<1, GV>>>();

    dim3 grid(GV / BN, NROW / BM);               // (5, 192)
    sgemm_kernel<<<grid, 256>>>(x, W, bias);

    epilogue_kernel<<<NROW / 32, 256>>>(gum, cb, out);

    finalize_kernel<<<1, GV>>>(out, out_size);
}